// round 13
// baseline (speedup 1.0000x reference)
#include <cuda_runtime.h>
#include <cuda_bf16.h>
#include <cuda_fp16.h>
#include <math.h>
#include <stdint.h>

#define B_   2
#define S_   2048
#define D_   1024
#define H_   16
#define DK_  64
#define DFF_ 4096
#define M_   (B_ * S_)

typedef __half hf;

// ---------------------------------------------------------------------------
// Scratch
// ---------------------------------------------------------------------------
__device__ float g_ffn[M_ * 2 * DFF_];   // reused as fp16 silu storage
__device__ float g_x2 [M_ * D_];
__device__ float2 g_rope[S_ * 32];

#define ASZ (16u * 1048576u)
#define WSZ (16u * 1048576u)
__device__ __nv_bfloat16 g_sh[ASZ];   // fp16 activation regions (q,k,v,h,attn)
__device__ hf g_w [WSZ];              // fp16 weights

// weight offsets; Q,K,V contiguous; W1,W3 interleaved at OW_1
#define OW_Q  0u
#define OW_O  3145728u
#define OW_1  4194304u
#define OW_2  12582912u
// activation regions (element offsets, 2B elems)
#define OQ_   0u
#define OK_   4194304u
#define OV_   8388608u
#define OA_   12582912u

// ---------------------------------------------------------------------------
// helpers
// ---------------------------------------------------------------------------
__device__ __forceinline__ uint32_t smem_u32(const void* p) {
    uint32_t a;
    asm("{ .reg .u64 t; cvta.to.shared.u64 t, %1; cvt.u32.u64 %0, t; }"
        : "=r"(a) : "l"(p));
    return a;
}
__device__ __forceinline__ void cp16(uint32_t dst, const void* src) {
    asm volatile("cp.async.cg.shared.global [%0], [%1], 16;"
                 :: "r"(dst), "l"(src));
}
__device__ __forceinline__ void ldm4(uint32_t* r, uint32_t a) {
    asm volatile("ldmatrix.sync.aligned.m8n8.x4.shared.b16 {%0,%1,%2,%3}, [%4];"
                 : "=r"(r[0]), "=r"(r[1]), "=r"(r[2]), "=r"(r[3]) : "r"(a));
}
__device__ __forceinline__ void ldm4t(uint32_t* r, uint32_t a) {
    asm volatile("ldmatrix.sync.aligned.m8n8.x4.trans.shared.b16 {%0,%1,%2,%3}, [%4];"
                 : "=r"(r[0]), "=r"(r[1]), "=r"(r[2]), "=r"(r[3]) : "r"(a));
}
__device__ __forceinline__ void mmah(float* c, const uint32_t* a,
                                     uint32_t b0, uint32_t b1) {
    asm volatile(
        "mma.sync.aligned.m16n8k16.row.col.f32.f16.f16.f32 "
        "{%0,%1,%2,%3}, {%4,%5,%6,%7}, {%8,%9}, {%0,%1,%2,%3};"
        : "+f"(c[0]), "+f"(c[1]), "+f"(c[2]), "+f"(c[3])
        : "r"(a[0]), "r"(a[1]), "r"(a[2]), "r"(a[3]), "r"(b0), "r"(b1));
}
__device__ __forceinline__ uint32_t packh2(float lo, float hi) {
    uint32_t r;
    asm("cvt.rn.f16x2.f32 %0, %1, %2;" : "=r"(r) : "f"(hi), "f"(lo));
    return r;
}
__device__ __forceinline__ uint2 cvt4h(const float4 v) {
    uint2 u;
    u.x = packh2(v.x, v.y);
    u.y = packh2(v.z, v.w);
    return u;
}

// ---------------------------------------------------------------------------
// weight converts (fp32 -> fp16)
// ---------------------------------------------------------------------------
__global__ void wconv3_kernel(const float* __restrict__ a,
                              const float* __restrict__ b,
                              const float* __restrict__ c,
                              hf* __restrict__ o) {
    int t = blockIdx.x * blockDim.x + threadIdx.x;
    if (t >= 262144) return;
    ((uint2*)o)[t]          = cvt4h(((const float4*)a)[t]);
    ((uint2*)o)[262144 + t] = cvt4h(((const float4*)b)[t]);
    ((uint2*)o)[524288 + t] = cvt4h(((const float4*)c)[t]);
}

__global__ void wconv_kernel(const float* __restrict__ s, hf* __restrict__ o, int n4) {
    int q = n4 >> 2;
    int t = blockIdx.x * blockDim.x + threadIdx.x;
    if (t >= q) return;
#pragma unroll
    for (int i = 0; i < 4; i++)
        ((uint2*)o)[t + i * q] = cvt4h(((const float4*)s)[t + i * q]);
}

__global__ void wconv13_kernel(const float* __restrict__ w1,
                               const float* __restrict__ w3,
                               hf* __restrict__ o) {
    int t = blockIdx.x * blockDim.x + threadIdx.x;
    if (t >= DFF_ * D_ / 4) return;
    int i = t >> 8, c = t & 255;
    ((uint2*)o)[(2 * i) * 256 + c]     = cvt4h(((const float4*)w1)[t]);
    ((uint2*)o)[(2 * i + 1) * 256 + c] = cvt4h(((const float4*)w3)[t]);
}

// ---------------------------------------------------------------------------
// single-pass fp16 GEMM mainloop, BK=64 staging, register-level fragment
// double buffering: prefetch step ks+1 ldmatrix while issuing ks MMAs.
// ---------------------------------------------------------------------------
#define LDSP    80
#define ARRSZ   10240
#define HALFSZ  20480
#define STAGE   40960
#define MG_SMEM (2 * STAGE)

__device__ __forceinline__ void ldfrag(
    uint32_t stg, int kk, int wm, int wn, int lane,
    uint32_t a[2][4], uint32_t b[4][4]) {
    uint32_t hb = stg + (kk >> 1) * HALFSZ;
    int ks = kk & 1;
    uint32_t ar = hb + (wm + (lane & 15)) * LDSP
                + (ks * 16 + (lane >> 4) * 8) * 2;
    ldm4(a[0], ar);
    ldm4(a[1], ar + 16 * LDSP);
    uint32_t br = hb + ARRSZ
                + (wn + (lane & 7) + ((lane >> 4) & 1) * 8) * LDSP
                + (ks * 16 + ((lane >> 3) & 1) * 8) * 2;
#pragma unroll
    for (int g = 0; g < 4; g++)
        ldm4(b[g], br + g * 16 * LDSP);
}

__device__ __forceinline__ void gemm_mainloop(
    uint32_t sb, int tid,
    const hf* pA, const hf* pB,
    int K, float acc[2][8][4]) {
    int wid = tid >> 5, lane = tid & 31;
    int wm = (wid & 3) * 32, wn = (wid >> 2) * 64;
    int nch = K >> 6;
    int jrow0 = tid >> 2;
    int jrow1 = 64 + jrow0;
    int kb = (tid & 3);

#define LOADCHUNK(c, s)                                                        \
    {                                                                          \
        int k0 = (c) << 6;                                                     \
        uint32_t stg = sb + (s) * STAGE;                                       \
        _Pragma("unroll")                                                      \
        for (int hh2 = 0; hh2 < 2; hh2++) {                                    \
            uint32_t hb = stg + hh2 * HALFSZ;                                  \
            {                                                                  \
                uint32_t db = hb + jrow0 * LDSP + kb * 16;                     \
                size_t go = (size_t)jrow0 * K + k0 + hh2 * 32 + kb * 8;        \
                cp16(db, pA + go);                                             \
                cp16(db + ARRSZ, pB + go);                                     \
            }                                                                  \
            {                                                                  \
                uint32_t db = hb + jrow1 * LDSP + kb * 16;                     \
                size_t go = (size_t)jrow1 * K + k0 + hh2 * 32 + kb * 8;        \
                cp16(db, pA + go);                                             \
                cp16(db + ARRSZ, pB + go);                                     \
            }                                                                  \
        }                                                                      \
        asm volatile("cp.async.commit_group;");                                \
    }

    LOADCHUNK(0, 0)

    uint32_t af[2][2][4], bf[2][4][4];

    for (int c = 0; c < nch; c++) {
        int s = c & 1;
        if (c + 1 < nch) {
            LOADCHUNK(c + 1, s ^ 1)
            asm volatile("cp.async.wait_group 1;");
        } else {
            asm volatile("cp.async.wait_group 0;");
        }
        __syncthreads();

        uint32_t stg = sb + s * STAGE;
        ldfrag(stg, 0, wm, wn, lane, af[0], bf[0]);
#pragma unroll
        for (int kk = 0; kk < 4; kk++) {
            int cur = kk & 1;
            if (kk < 3)
                ldfrag(stg, kk + 1, wm, wn, lane, af[cur ^ 1], bf[cur ^ 1]);
#pragma unroll
            for (int g = 0; g < 4; g++) {
                mmah(acc[0][2 * g],     af[cur][0], bf[cur][g][0], bf[cur][g][1]);
                mmah(acc[0][2 * g + 1], af[cur][0], bf[cur][g][2], bf[cur][g][3]);
                mmah(acc[1][2 * g],     af[cur][1], bf[cur][g][0], bf[cur][g][1]);
                mmah(acc[1][2 * g + 1], af[cur][1], bf[cur][g][2], bf[cur][g][3]);
            }
        }
        __syncthreads();
    }
}

// ---------------------------------------------------------------------------
// generic GEMM: C fp32 (+R)
// ---------------------------------------------------------------------------
__global__ __launch_bounds__(256, 2) void mma_gemm_kernel(
    const hf* __restrict__ A, const hf* __restrict__ Bm,
    const float* __restrict__ R, float* __restrict__ C,
    int M, int N, int K) {
    extern __shared__ char smx[];
    uint32_t sb = smem_u32(smx);
    int tid = threadIdx.x, wid = tid >> 5, lane = tid & 31;
    int bm = blockIdx.y * 128, bn = blockIdx.x * 128;
    int wm = (wid & 3) * 32, wn = (wid >> 2) * 64;

    float acc[2][8][4];
#pragma unroll
    for (int i = 0; i < 2; i++)
#pragma unroll
        for (int j = 0; j < 8; j++)
#pragma unroll
            for (int t = 0; t < 4; t++) acc[i][j][t] = 0.f;

    gemm_mainloop(sb, tid, A + (size_t)bm * K, Bm + (size_t)bn * K, K, acc);

#pragma unroll
    for (int mt = 0; mt < 2; mt++) {
        int m0 = bm + wm + mt * 16 + (lane >> 2);
#pragma unroll
        for (int nt = 0; nt < 8; nt++) {
            int n0 = bn + wn + nt * 8 + (lane & 3) * 2;
            float2 v0 = make_float2(acc[mt][nt][0], acc[mt][nt][1]);
            float2 v1 = make_float2(acc[mt][nt][2], acc[mt][nt][3]);
            if (R) {
                float2 r0 = *(const float2*)(R + (size_t)m0 * N + n0);
                float2 r1 = *(const float2*)(R + (size_t)(m0 + 8) * N + n0);
                v0.x += r0.x; v0.y += r0.y;
                v1.x += r1.x; v1.y += r1.y;
            }
            *(float2*)(C + (size_t)m0 * N + n0) = v0;
            *(float2*)(C + (size_t)(m0 + 8) * N + n0) = v1;
        }
    }
}

// ---------------------------------------------------------------------------
// qkv GEMM (N=3072): epilogue RoPE + single-fp16 write + [b,h,s,dk] repack
// ---------------------------------------------------------------------------
__global__ __launch_bounds__(256, 2) void mma_gemm_qkv_kernel(
    const hf* __restrict__ A, const hf* __restrict__ Bm,
    const float2* __restrict__ tab,
    hf* __restrict__ oq) {
    extern __shared__ char smx[];
    uint32_t sb = smem_u32(smx);
    int tid = threadIdx.x, wid = tid >> 5, lane = tid & 31;
    int bm = blockIdx.y * 128, bn = blockIdx.x * 128;
    int wm = (wid & 3) * 32, wn = (wid >> 2) * 64;
    const int K = D_;

    float acc[2][8][4];
#pragma unroll
    for (int i = 0; i < 2; i++)
#pragma unroll
        for (int j = 0; j < 8; j++)
#pragma unroll
            for (int t = 0; t < 4; t++) acc[i][j][t] = 0.f;

    gemm_mainloop(sb, tid, A + (size_t)bm * K, Bm + (size_t)bn * K, K, acc);

#pragma unroll
    for (int nt = 0; nt < 8; nt++) {
        int n0 = bn + wn + nt * 8 + (lane & 3) * 2;
        int sec = n0 >> 10;
        int d = n0 & 1023;
        int hh = d >> 6;
        int dk = d & 63;
        uint32_t obase = sec * 4194304u;
#pragma unroll
        for (int mt = 0; mt < 2; mt++) {
            int m0 = bm + wm + mt * 16 + (lane >> 2);
#pragma unroll
            for (int rr = 0; rr < 2; rr++) {
                int m = m0 + rr * 8;
                int s = m & (S_ - 1);
                int b = m >> 11;
                float e = acc[mt][nt][rr * 2], o = acc[mt][nt][rr * 2 + 1];
                if (sec < 2) {
                    float2 cs = tab[(s << 5) + (dk >> 1)];
                    float e2 = cs.x * e - cs.y * o;
                    o = cs.y * e + cs.x * o;
                    e = e2;
                }
                size_t off = obase + ((size_t)(b * H_ + hh) * S_ + s) * DK_ + dk;
                *(uint32_t*)(oq + off) = packh2(e, o);
            }
        }
    }
}

// ---------------------------------------------------------------------------
// w1|w3 GEMM + SwiGLU: N=8192 interleaved (even=u, odd=g); writes fp16 silu
// ---------------------------------------------------------------------------
__global__ __launch_bounds__(256, 2) void mma_gemm_swiglu_kernel(
    const hf* __restrict__ A, const hf* __restrict__ Bm,
    hf* __restrict__ outp) {
    extern __shared__ char smx[];
    uint32_t sb = smem_u32(smx);
    int tid = threadIdx.x, wid = tid >> 5, lane = tid & 31;
    int bm = blockIdx.y * 128, bn = blockIdx.x * 128;
    int wm = (wid & 3) * 32, wn = (wid >> 2) * 64;
    const int K = D_;

    float acc[2][8][4];
#pragma unroll
    for (int i = 0; i < 2; i++)
#pragma unroll
        for (int j = 0; j < 8; j++)
#pragma unroll
            for (int t = 0; t < 4; t++) acc[i][j][t] = 0.f;

    gemm_mainloop(sb, tid, A + (size_t)bm * K, Bm + (size_t)bn * K, K, acc);

#pragma unroll
    for (int mt = 0; mt < 2; mt++) {
        int m0 = bm + wm + mt * 16 + (lane >> 2);
#pragma unroll
        for (int nt = 0; nt < 8; nt++) {
            int f0 = (bn + wn + nt * 8 + (lane & 3) * 2) >> 1;
#pragma unroll
            for (int rr = 0; rr < 2; rr++) {
                int m = m0 + rr * 8;
                float u = acc[mt][nt][rr * 2];
                float g = acc[mt][nt][rr * 2 + 1];
                float r = u * (1.0f / (1.0f + __expf(-u))) * g;
                outp[(size_t)m * DFF_ + f0] = __float2half_rn(r);
            }
        }
    }
}

// ---------------------------------------------------------------------------
// RoPE table (double precision)
// ---------------------------------------------------------------------------
__global__ void rope_table_kernel(float2* __restrict__ tab) {
    int idx = blockIdx.x * blockDim.x + threadIdx.x;
    if (idx >= S_ * 32) return;
    int s = idx >> 5;
    int i = idx & 31;
    double invf = exp2(-(double)(2 * i) * (13.287712379549449 / 64.0));
    double ang = (double)s * invf;
    double sd, cd;
    sincos(ang, &sd, &cd);
    tab[idx] = make_float2((float)cd, (float)sd);
}

// ---------------------------------------------------------------------------
// RMSNorm -> single fp16
// ---------------------------------------------------------------------------
__global__ __launch_bounds__(256) void rmsnorm_h_kernel(
    const float* __restrict__ x, const float* __restrict__ w,
    hf* __restrict__ out) {
    int row = blockIdx.x;
    const float4* xr = (const float4*)(x + (size_t)row * D_);
    int i = threadIdx.x;
    float4 xv = xr[i];
    float ss = xv.x * xv.x + xv.y * xv.y + xv.z * xv.z + xv.w * xv.w;
#pragma unroll
    for (int off = 16; off > 0; off >>= 1)
        ss += __shfl_xor_sync(0xffffffffu, ss, off);
    __shared__ float red[8];
    __shared__ float s_inv;
    if ((threadIdx.x & 31) == 0) red[threadIdx.x >> 5] = ss;
    __syncthreads();
    if (threadIdx.x == 0) {
        float t = 0.f;
#pragma unroll
        for (int j = 0; j < 8; j++) t += red[j];
        s_inv = rsqrtf(t * (1.0f / D_) + 1e-5f);
    }
    __syncthreads();
    float inv = s_inv;
    float4 wv = ((const float4*)w)[i];
    uint2 o;
    o.x = packh2(inv * xv.x * wv.x, inv * xv.y * wv.y);
    o.y = packh2(inv * xv.z * wv.z, inv * xv.w * wv.w);
    ((uint2*)(out + (size_t)row * D_))[i] = o;
}

// ---------------------------------------------------------------------------
// Single-fp16 HMMA causal flash attention, 2-stage KV cp.async pipeline.
// ---------------------------------------------------------------------------
#define AP     144
#define ATQ    0
#define ATKV   9216
#define AT_SMEM (9216 + 2 * 18432)

__global__ __launch_bounds__(128, 3) void attn_mma_kernel(
    const hf* __restrict__ qg, const hf* __restrict__ kg,
    const hf* __restrict__ vg, hf* __restrict__ oh) {
    extern __shared__ char smx[];
    uint32_t sb = smem_u32(smx);
    int tid = threadIdx.x, w = tid >> 5, lane = tid & 31;
    int qt = gridDim.x - 1 - blockIdx.x;
    int h = blockIdx.y, b = blockIdx.z;
    size_t base = (size_t)(b * H_ + h) * S_;
    int s0 = qt * 64;

#pragma unroll
    for (int i = 0; i < 4; i++) {
        int idx = i * 128 + tid;
        int row = idx >> 3, c = idx & 7;
        cp16(sb + ATQ + row * AP + c * 16, qg + (base + s0 + row) * DK_ + c * 8);
    }
    asm volatile("cp.async.commit_group;");

#define LOADKV(t, s)                                                           \
    {                                                                          \
        uint32_t kvb = sb + ATKV + (s) * 18432;                                \
        _Pragma("unroll")                                                      \
        for (int i = 0; i < 4; i++) {                                          \
            int idx = i * 128 + tid;                                           \
            int row = idx >> 3, c = idx & 7;                                   \
            size_t go = (base + (t) * 64 + row) * DK_ + c * 8;                 \
            cp16(kvb + row * AP + c * 16, kg + go);                            \
            cp16(kvb + 9216 + row * AP + c * 16, vg + go);                     \
        }                                                                      \
        asm volatile("cp.async.commit_group;");                                \
    }

    LOADKV(0, 0)
    asm volatile("cp.async.wait_group 1;");
    __syncthreads();

    uint32_t qf[4][4];
#pragma unroll
    for (int ks = 0; ks < 4; ks++) {
        uint32_t ar = sb + ATQ + (16 * w + (lane & 15)) * AP
                    + (ks * 16 + (lane >> 4) * 8) * 2;
        ldm4(qf[ks], ar);
    }

    float oacc[8][4];
#pragma unroll
    for (int j = 0; j < 8; j++)
#pragma unroll
        for (int t = 0; t < 4; t++) oacc[j][t] = 0.f;
    float m0 = -INFINITY, m1 = -INFINITY, l0 = 0.f, l1 = 0.f;
    int q0 = s0 + 16 * w + (lane >> 2);

    for (int kvt = 0; kvt <= qt; kvt++) {
        int s = kvt & 1;
        if (kvt < qt) {
            LOADKV(kvt + 1, s ^ 1)
            asm volatile("cp.async.wait_group 1;");
        } else {
            asm volatile("cp.async.wait_group 0;");
        }
        __syncthreads();

        uint32_t kvb = sb + ATKV + s * 18432;
        float sacc[8][4];
#pragma unroll
        for (int j = 0; j < 8; j++)
#pragma unroll
            for (int t = 0; t < 4; t++) sacc[j][t] = 0.f;
#pragma unroll
        for (int ks = 0; ks < 4; ks++) {
            uint32_t br = kvb + ((lane & 7) + ((lane >> 4) & 1) * 8) * AP
                        + (ks * 16 + ((lane >> 3) & 1) * 8) * 2;
#pragma unroll
            for (int g = 0; g < 4; g++) {
                uint32_t b4[4];
                ldm4(b4, br + g * 16 * AP);
                mmah(sacc[2 * g],     qf[ks], b4[0], b4[1]);
                mmah(sacc[2 * g + 1], qf[ks], b4[2], b4[3]);
            }
        }
#pragma unroll
        for (int j = 0; j < 8; j++)
#pragma unroll
            for (int t = 0; t < 4; t++) sacc[j][t] *= 0.125f;
        if (kvt == qt) {
            int cb = kvt * 64 + 2 * (lane & 3);
#pragma unroll
            for (int j = 0; j < 8; j++) {
                int kc = cb + 8 * j;
                if (kc     > q0)     sacc[j][0] = -INFINITY;
                if (kc + 1 > q0)     sacc[j][1] = -INFINITY;
                if (kc     > q0 + 8) sacc[j][2] = -INFINITY;
                if (kc + 1 > q0 + 8) sacc[j][3] = -INFINITY;
            }
        }
        float mx0 = -INFINITY, mx1 = -INFINITY;
#pragma unroll
        for (int j = 0; j < 8; j++) {
            mx0 = fmaxf(mx0, fmaxf(sacc[j][0], sacc[j][1]));
            mx1 = fmaxf(mx1, fmaxf(sacc[j][2], sacc[j][3]));
        }
        mx0 = fmaxf(mx0, __shfl_xor_sync(0xffffffffu, mx0, 1));
        mx0 = fmaxf(mx0, __shfl_xor_sync(0xffffffffu, mx0, 2));
        mx1 = fmaxf(mx1, __shfl_xor_sync(0xffffffffu, mx1, 1));
        mx1 = fmaxf(mx1, __shfl_xor_sync(0xffffffffu, mx1, 2));
        float mn0 = fmaxf(m0, mx0), mn1 = fmaxf(m1, mx1);
        float cr0 = __expf(m0 - mn0), cr1 = __expf(m1 - mn1);
        l0 *= cr0; l1 *= cr1;
#pragma unroll
        for (int j = 0; j < 8; j++) {
            oacc[j][0] *= cr0; oacc[j][1] *= cr0;
            oacc[j][2] *= cr1; oacc[j][3] *= cr1;
        }
        uint32_t pf[4][4];
#pragma unroll
        for (int j = 0; j < 8; j++) {
            float p0 = __expf(sacc[j][0] - mn0);
            float p1 = __expf(sacc[j][1] - mn0);
            float p2 = __expf(sacc[j][2] - mn1);
            float p3 = __expf(sacc[j][3] - mn1);
            l0 += p0 + p1; l1 += p2 + p3;
            pf[j >> 1][(j & 1) * 2]     = packh2(p0, p1);
            pf[j >> 1][(j & 1) * 2 + 1] = packh2(p2, p3);
        }
        m0 = mn0; m1 = mn1;
#pragma unroll
        for (int kt = 0; kt < 4; kt++) {
            uint32_t va = kvb + 9216 + (kt * 16 + (lane & 15)) * AP
                        + ((lane >> 4) * 8) * 2;
#pragma unroll
            for (int gn = 0; gn < 4; gn++) {
                uint32_t vb[4];
                ldm4t(vb, va + gn * 32);
                mmah(oacc[2 * gn],     pf[kt], vb[0], vb[1]);
                mmah(oacc[2 * gn + 1], pf[kt], vb[2], vb[3]);
            }
        }
        __syncthreads();
    }

    l0 += __shfl_xor_sync(0xffffffffu, l0, 1);
    l0 += __shfl_xor_sync(0xffffffffu, l0, 2);
    l1 += __shfl_xor_sync(0xffffffffu, l1, 1);
    l1 += __shfl_xor_sync(0xffffffffu, l1, 2);
    float i0 = 1.f / l0, i1 = 1.f / l1;

    size_t r0 = (size_t)(b * S_ + q0) * D_ + h * DK_;
    size_t r1 = (size_t)(b * S_ + q0 + 8) * D_ + h * DK_;
#pragma unroll
    for (int j = 0; j < 8; j++) {
        int dk0 = 8 * j + 2 * (lane & 3);
        *(uint32_t*)(oh + r0 + dk0) = packh2(oacc[j][0] * i0, oacc[j][1] * i0);
        *(uint32_t*)(oh + r1 + dk0) = packh2(oacc[j][2] * i1, oacc[j][3] * i1);
    }
}

// ---------------------------------------------------------------------------
// Launch (launch index 3 == qkv GEMM, targeted by ncu -s 5 -c 1)
// ---------------------------------------------------------------------------
extern "C" void kernel_launch(void* const* d_in, const int* in_sizes, int n_in,
                              void* d_out, int out_size) {
    const float* x   = (const float*)d_in[0];
    const float* w_q = (const float*)d_in[1];
    const float* w_k = (const float*)d_in[2];
    const float* w_v = (const float*)d_in[3];
    const float* w_o = (const float*)d_in[4];
    const float* ln1 = (const float*)d_in[5];
    const float* ln2 = (const float*)d_in[6];
    const float* w1  = (const float*)d_in[7];
    const float* w2  = (const float*)d_in[8];
    const float* w3  = (const float*)d_in[9];
    float* out = (float*)d_out;

    float *ffn, *x2;
    float2* rope;
    __nv_bfloat16 *sh;
    hf* wp;
    cudaGetSymbolAddress((void**)&ffn,  g_ffn);
    cudaGetSymbolAddress((void**)&x2,   g_x2);
    cudaGetSymbolAddress((void**)&rope, g_rope);
    cudaGetSymbolAddress((void**)&sh,   g_sh);
    cudaGetSymbolAddress((void**)&wp,   g_w);
    hf* qA    = (hf*)sh + OQ_;
    hf* kA    = (hf*)sh + OK_;
    hf* vA    = (hf*)sh + OV_;
    hf* hA    = (hf*)sh + OA_;
    hf* h2A   = (hf*)sh;
    hf* siluA = (hf*)ffn;

    cudaFuncSetAttribute(mma_gemm_kernel,
                         cudaFuncAttributeMaxDynamicSharedMemorySize, MG_SMEM);
    cudaFuncSetAttribute(mma_gemm_qkv_kernel,
                         cudaFuncAttributeMaxDynamicSharedMemorySize, MG_SMEM);
    cudaFuncSetAttribute(mma_gemm_swiglu_kernel,
                         cudaFuncAttributeMaxDynamicSharedMemorySize, MG_SMEM);
    cudaFuncSetAttribute(attn_mma_kernel,
                         cudaFuncAttributeMaxDynamicSharedMemorySize, AT_SMEM);

    // 0..2
    rope_table_kernel<<<(S_ * 32 + 255) / 256, 256>>>(rope);
    rmsnorm_h_kernel<<<M_, 256>>>(x, ln1, hA);
    wconv3_kernel<<<1024, 256>>>(w_q, w_k, w_v, wp + OW_Q);

    // 3 (ncu target): qkv GEMM -> roped fp16 q,k,v in [b,h,s,dk]
    mma_gemm_qkv_kernel<<<dim3(3072 / 128, M_ / 128), 256, MG_SMEM>>>(
        hA, wp + OW_Q, rope, (hf*)sh);

    // remaining weight converts
    wconv_kernel<<<256, 256>>>(w_o, wp + OW_O, 262144);
    wconv13_kernel<<<4096, 256>>>(w1, w3, wp + OW_1);
    wconv_kernel<<<1024, 256>>>(w2, wp + OW_2, 1048576);

    // attention -> fp16 at OA_
    attn_mma_kernel<<<dim3(S_ / 64, H_, B_), 128, AT_SMEM>>>(qA, kA, vA, hA);

    // x2 = x + attn @ w_o^T
    mma_gemm_kernel<<<dim3(D_ / 128, M_ / 128), 256, MG_SMEM>>>(
        hA, wp + OW_O, x, x2, M_, D_, D_);

    // h2 = rmsnorm(x2)
    rmsnorm_h_kernel<<<M_, 256>>>(x2, ln2, h2A);

    // [u|g] GEMM + SwiGLU
    mma_gemm_swiglu_kernel<<<dim3(8192 / 128, M_ / 128), 256, MG_SMEM>>>(
        h2A, wp + OW_1, siluA);

    // out = x2 + silu @ w2^T
    mma_gemm_kernel<<<dim3(D_ / 128, M_ / 128), 256, MG_SMEM>>>(
        siluA, wp + OW_2, x2, out, M_, D_, DFF_);
}

// round 14
// speedup vs baseline: 1.0042x; 1.0042x over previous
#include <cuda_runtime.h>
#include <cuda_bf16.h>
#include <cuda_fp16.h>
#include <math.h>
#include <stdint.h>

#define B_   2
#define S_   2048
#define D_   1024
#define H_   16
#define DK_  64
#define DFF_ 4096
#define M_   (B_ * S_)

typedef __half hf;

// ---------------------------------------------------------------------------
// Scratch
// ---------------------------------------------------------------------------
__device__ float g_ffn[M_ * 2 * DFF_];   // reused as fp16 silu storage
__device__ float g_x2 [M_ * D_];
__device__ float2 g_rope[S_ * 32];

#define ASZ (16u * 1048576u)
#define WSZ (16u * 1048576u)
__device__ __nv_bfloat16 g_sh[ASZ];   // fp16 activation regions (q,k,v,h,attn)
__device__ hf g_w [WSZ];              // fp16 weights

// weight offsets; Q,K,V contiguous; W1,W3 interleaved at OW_1
#define OW_Q  0u
#define OW_O  3145728u
#define OW_1  4194304u
#define OW_2  12582912u
// activation regions (element offsets, 2B elems)
#define OQ_   0u
#define OK_   4194304u
#define OV_   8388608u
#define OA_   12582912u

// ---------------------------------------------------------------------------
// helpers
// ---------------------------------------------------------------------------
__device__ __forceinline__ uint32_t smem_u32(const void* p) {
    uint32_t a;
    asm("{ .reg .u64 t; cvta.to.shared.u64 t, %1; cvt.u32.u64 %0, t; }"
        : "=r"(a) : "l"(p));
    return a;
}
__device__ __forceinline__ void cp16(uint32_t dst, const void* src) {
    asm volatile("cp.async.cg.shared.global [%0], [%1], 16;"
                 :: "r"(dst), "l"(src));
}
__device__ __forceinline__ void ldm4(uint32_t* r, uint32_t a) {
    asm volatile("ldmatrix.sync.aligned.m8n8.x4.shared.b16 {%0,%1,%2,%3}, [%4];"
                 : "=r"(r[0]), "=r"(r[1]), "=r"(r[2]), "=r"(r[3]) : "r"(a));
}
__device__ __forceinline__ void ldm4t(uint32_t* r, uint32_t a) {
    asm volatile("ldmatrix.sync.aligned.m8n8.x4.trans.shared.b16 {%0,%1,%2,%3}, [%4];"
                 : "=r"(r[0]), "=r"(r[1]), "=r"(r[2]), "=r"(r[3]) : "r"(a));
}
__device__ __forceinline__ void mmah(float* c, const uint32_t* a,
                                     uint32_t b0, uint32_t b1) {
    asm volatile(
        "mma.sync.aligned.m16n8k16.row.col.f32.f16.f16.f32 "
        "{%0,%1,%2,%3}, {%4,%5,%6,%7}, {%8,%9}, {%0,%1,%2,%3};"
        : "+f"(c[0]), "+f"(c[1]), "+f"(c[2]), "+f"(c[3])
        : "r"(a[0]), "r"(a[1]), "r"(a[2]), "r"(a[3]), "r"(b0), "r"(b1));
}
__device__ __forceinline__ uint32_t packh2(float lo, float hi) {
    uint32_t r;
    asm("cvt.rn.f16x2.f32 %0, %1, %2;" : "=r"(r) : "f"(hi), "f"(lo));
    return r;
}
__device__ __forceinline__ uint2 cvt4h(const float4 v) {
    uint2 u;
    u.x = packh2(v.x, v.y);
    u.y = packh2(v.z, v.w);
    return u;
}

// ---------------------------------------------------------------------------
// weight converts (fp32 -> fp16)
// ---------------------------------------------------------------------------
__global__ void wconv3_kernel(const float* __restrict__ a,
                              const float* __restrict__ b,
                              const float* __restrict__ c,
                              hf* __restrict__ o) {
    int t = blockIdx.x * blockDim.x + threadIdx.x;
    if (t >= 262144) return;
    ((uint2*)o)[t]          = cvt4h(((const float4*)a)[t]);
    ((uint2*)o)[262144 + t] = cvt4h(((const float4*)b)[t]);
    ((uint2*)o)[524288 + t] = cvt4h(((const float4*)c)[t]);
}

__global__ void wconv_kernel(const float* __restrict__ s, hf* __restrict__ o, int n4) {
    int q = n4 >> 2;
    int t = blockIdx.x * blockDim.x + threadIdx.x;
    if (t >= q) return;
#pragma unroll
    for (int i = 0; i < 4; i++)
        ((uint2*)o)[t + i * q] = cvt4h(((const float4*)s)[t + i * q]);
}

__global__ void wconv13_kernel(const float* __restrict__ w1,
                               const float* __restrict__ w3,
                               hf* __restrict__ o) {
    int t = blockIdx.x * blockDim.x + threadIdx.x;
    if (t >= DFF_ * D_ / 4) return;
    int i = t >> 8, c = t & 255;
    ((uint2*)o)[(2 * i) * 256 + c]     = cvt4h(((const float4*)w1)[t]);
    ((uint2*)o)[(2 * i + 1) * 256 + c] = cvt4h(((const float4*)w3)[t]);
}

// ---------------------------------------------------------------------------
// single-pass fp16 GEMM mainloop, BK=64 staging, register-level fragment
// double buffering: prefetch step ks+1 ldmatrix while issuing ks MMAs.
// ---------------------------------------------------------------------------
#define LDSP    80
#define ARRSZ   10240
#define HALFSZ  20480
#define STAGE   40960
#define MG_SMEM (2 * STAGE)

__device__ __forceinline__ void ldfrag(
    uint32_t stg, int kk, int wm, int wn, int lane,
    uint32_t a[2][4], uint32_t b[4][4]) {
    uint32_t hb = stg + (kk >> 1) * HALFSZ;
    int ks = kk & 1;
    uint32_t ar = hb + (wm + (lane & 15)) * LDSP
                + (ks * 16 + (lane >> 4) * 8) * 2;
    ldm4(a[0], ar);
    ldm4(a[1], ar + 16 * LDSP);
    uint32_t br = hb + ARRSZ
                + (wn + (lane & 7) + ((lane >> 4) & 1) * 8) * LDSP
                + (ks * 16 + ((lane >> 3) & 1) * 8) * 2;
#pragma unroll
    for (int g = 0; g < 4; g++)
        ldm4(b[g], br + g * 16 * LDSP);
}

__device__ __forceinline__ void gemm_mainloop(
    uint32_t sb, int tid,
    const hf* pA, const hf* pB,
    int K, float acc[2][8][4]) {
    int wid = tid >> 5, lane = tid & 31;
    int wm = (wid & 3) * 32, wn = (wid >> 2) * 64;
    int nch = K >> 6;
    int jrow0 = tid >> 2;
    int jrow1 = 64 + jrow0;
    int kb = (tid & 3);

#define LOADCHUNK(c, s)                                                        \
    {                                                                          \
        int k0 = (c) << 6;                                                     \
        uint32_t stg = sb + (s) * STAGE;                                       \
        _Pragma("unroll")                                                      \
        for (int hh2 = 0; hh2 < 2; hh2++) {                                    \
            uint32_t hb = stg + hh2 * HALFSZ;                                  \
            {                                                                  \
                uint32_t db = hb + jrow0 * LDSP + kb * 16;                     \
                size_t go = (size_t)jrow0 * K + k0 + hh2 * 32 + kb * 8;        \
                cp16(db, pA + go);                                             \
                cp16(db + ARRSZ, pB + go);                                     \
            }                                                                  \
            {                                                                  \
                uint32_t db = hb + jrow1 * LDSP + kb * 16;                     \
                size_t go = (size_t)jrow1 * K + k0 + hh2 * 32 + kb * 8;        \
                cp16(db, pA + go);                                             \
                cp16(db + ARRSZ, pB + go);                                     \
            }                                                                  \
        }                                                                      \
        asm volatile("cp.async.commit_group;");                                \
    }

    LOADCHUNK(0, 0)

    uint32_t af[2][2][4], bf[2][4][4];

    for (int c = 0; c < nch; c++) {
        int s = c & 1;
        if (c + 1 < nch) {
            LOADCHUNK(c + 1, s ^ 1)
            asm volatile("cp.async.wait_group 1;");
        } else {
            asm volatile("cp.async.wait_group 0;");
        }
        __syncthreads();

        uint32_t stg = sb + s * STAGE;
        ldfrag(stg, 0, wm, wn, lane, af[0], bf[0]);
#pragma unroll
        for (int kk = 0; kk < 4; kk++) {
            int cur = kk & 1;
            if (kk < 3)
                ldfrag(stg, kk + 1, wm, wn, lane, af[cur ^ 1], bf[cur ^ 1]);
#pragma unroll
            for (int g = 0; g < 4; g++) {
                mmah(acc[0][2 * g],     af[cur][0], bf[cur][g][0], bf[cur][g][1]);
                mmah(acc[0][2 * g + 1], af[cur][0], bf[cur][g][2], bf[cur][g][3]);
                mmah(acc[1][2 * g],     af[cur][1], bf[cur][g][0], bf[cur][g][1]);
                mmah(acc[1][2 * g + 1], af[cur][1], bf[cur][g][2], bf[cur][g][3]);
            }
        }
        __syncthreads();
    }
}

// ---------------------------------------------------------------------------
// generic GEMM: C fp32 (+R)
// ---------------------------------------------------------------------------
__global__ __launch_bounds__(256, 2) void mma_gemm_kernel(
    const hf* __restrict__ A, const hf* __restrict__ Bm,
    const float* __restrict__ R, float* __restrict__ C,
    int M, int N, int K) {
    extern __shared__ char smx[];
    uint32_t sb = smem_u32(smx);
    int tid = threadIdx.x, wid = tid >> 5, lane = tid & 31;
    int bm = blockIdx.y * 128, bn = blockIdx.x * 128;
    int wm = (wid & 3) * 32, wn = (wid >> 2) * 64;

    float acc[2][8][4];
#pragma unroll
    for (int i = 0; i < 2; i++)
#pragma unroll
        for (int j = 0; j < 8; j++)
#pragma unroll
            for (int t = 0; t < 4; t++) acc[i][j][t] = 0.f;

    gemm_mainloop(sb, tid, A + (size_t)bm * K, Bm + (size_t)bn * K, K, acc);

#pragma unroll
    for (int mt = 0; mt < 2; mt++) {
        int m0 = bm + wm + mt * 16 + (lane >> 2);
#pragma unroll
        for (int nt = 0; nt < 8; nt++) {
            int n0 = bn + wn + nt * 8 + (lane & 3) * 2;
            float2 v0 = make_float2(acc[mt][nt][0], acc[mt][nt][1]);
            float2 v1 = make_float2(acc[mt][nt][2], acc[mt][nt][3]);
            if (R) {
                float2 r0 = *(const float2*)(R + (size_t)m0 * N + n0);
                float2 r1 = *(const float2*)(R + (size_t)(m0 + 8) * N + n0);
                v0.x += r0.x; v0.y += r0.y;
                v1.x += r1.x; v1.y += r1.y;
            }
            *(float2*)(C + (size_t)m0 * N + n0) = v0;
            *(float2*)(C + (size_t)(m0 + 8) * N + n0) = v1;
        }
    }
}

// ---------------------------------------------------------------------------
// qkv GEMM (N=3072): epilogue RoPE + single-fp16 write + [b,h,s,dk] repack
// ---------------------------------------------------------------------------
__global__ __launch_bounds__(256, 2) void mma_gemm_qkv_kernel(
    const hf* __restrict__ A, const hf* __restrict__ Bm,
    const float2* __restrict__ tab,
    hf* __restrict__ oq) {
    extern __shared__ char smx[];
    uint32_t sb = smem_u32(smx);
    int tid = threadIdx.x, wid = tid >> 5, lane = tid & 31;
    int bm = blockIdx.y * 128, bn = blockIdx.x * 128;
    int wm = (wid & 3) * 32, wn = (wid >> 2) * 64;
    const int K = D_;

    float acc[2][8][4];
#pragma unroll
    for (int i = 0; i < 2; i++)
#pragma unroll
        for (int j = 0; j < 8; j++)
#pragma unroll
            for (int t = 0; t < 4; t++) acc[i][j][t] = 0.f;

    gemm_mainloop(sb, tid, A + (size_t)bm * K, Bm + (size_t)bn * K, K, acc);

#pragma unroll
    for (int nt = 0; nt < 8; nt++) {
        int n0 = bn + wn + nt * 8 + (lane & 3) * 2;
        int sec = n0 >> 10;
        int d = n0 & 1023;
        int hh = d >> 6;
        int dk = d & 63;
        uint32_t obase = sec * 4194304u;
#pragma unroll
        for (int mt = 0; mt < 2; mt++) {
            int m0 = bm + wm + mt * 16 + (lane >> 2);
#pragma unroll
            for (int rr = 0; rr < 2; rr++) {
                int m = m0 + rr * 8;
                int s = m & (S_ - 1);
                int b = m >> 11;
                float e = acc[mt][nt][rr * 2], o = acc[mt][nt][rr * 2 + 1];
                if (sec < 2) {
                    float2 cs = tab[(s << 5) + (dk >> 1)];
                    float e2 = cs.x * e - cs.y * o;
                    o = cs.y * e + cs.x * o;
                    e = e2;
                }
                size_t off = obase + ((size_t)(b * H_ + hh) * S_ + s) * DK_ + dk;
                *(uint32_t*)(oq + off) = packh2(e, o);
            }
        }
    }
}

// ---------------------------------------------------------------------------
// w1|w3 GEMM + SwiGLU: N=8192 interleaved (even=u, odd=g); writes fp16 silu
// ---------------------------------------------------------------------------
__global__ __launch_bounds__(256, 2) void mma_gemm_swiglu_kernel(
    const hf* __restrict__ A, const hf* __restrict__ Bm,
    hf* __restrict__ outp) {
    extern __shared__ char smx[];
    uint32_t sb = smem_u32(smx);
    int tid = threadIdx.x, wid = tid >> 5, lane = tid & 31;
    int bm = blockIdx.y * 128, bn = blockIdx.x * 128;
    int wm = (wid & 3) * 32, wn = (wid >> 2) * 64;
    const int K = D_;

    float acc[2][8][4];
#pragma unroll
    for (int i = 0; i < 2; i++)
#pragma unroll
        for (int j = 0; j < 8; j++)
#pragma unroll
            for (int t = 0; t < 4; t++) acc[i][j][t] = 0.f;

    gemm_mainloop(sb, tid, A + (size_t)bm * K, Bm + (size_t)bn * K, K, acc);

#pragma unroll
    for (int mt = 0; mt < 2; mt++) {
        int m0 = bm + wm + mt * 16 + (lane >> 2);
#pragma unroll
        for (int nt = 0; nt < 8; nt++) {
            int f0 = (bn + wn + nt * 8 + (lane & 3) * 2) >> 1;
#pragma unroll
            for (int rr = 0; rr < 2; rr++) {
                int m = m0 + rr * 8;
                float u = acc[mt][nt][rr * 2];
                float g = acc[mt][nt][rr * 2 + 1];
                float r = u * (1.0f / (1.0f + __expf(-u))) * g;
                outp[(size_t)m * DFF_ + f0] = __float2half_rn(r);
            }
        }
    }
}

// ---------------------------------------------------------------------------
// RoPE table (double precision)
// ---------------------------------------------------------------------------
__global__ void rope_table_kernel(float2* __restrict__ tab) {
    int idx = blockIdx.x * blockDim.x + threadIdx.x;
    if (idx >= S_ * 32) return;
    int s = idx >> 5;
    int i = idx & 31;
    double invf = exp2(-(double)(2 * i) * (13.287712379549449 / 64.0));
    double ang = (double)s * invf;
    double sd, cd;
    sincos(ang, &sd, &cd);
    tab[idx] = make_float2((float)cd, (float)sd);
}

// ---------------------------------------------------------------------------
// RMSNorm -> single fp16
// ---------------------------------------------------------------------------
__global__ __launch_bounds__(256) void rmsnorm_h_kernel(
    const float* __restrict__ x, const float* __restrict__ w,
    hf* __restrict__ out) {
    int row = blockIdx.x;
    const float4* xr = (const float4*)(x + (size_t)row * D_);
    int i = threadIdx.x;
    float4 xv = xr[i];
    float ss = xv.x * xv.x + xv.y * xv.y + xv.z * xv.z + xv.w * xv.w;
#pragma unroll
    for (int off = 16; off > 0; off >>= 1)
        ss += __shfl_xor_sync(0xffffffffu, ss, off);
    __shared__ float red[8];
    __shared__ float s_inv;
    if ((threadIdx.x & 31) == 0) red[threadIdx.x >> 5] = ss;
    __syncthreads();
    if (threadIdx.x == 0) {
        float t = 0.f;
#pragma unroll
        for (int j = 0; j < 8; j++) t += red[j];
        s_inv = rsqrtf(t * (1.0f / D_) + 1e-5f);
    }
    __syncthreads();
    float inv = s_inv;
    float4 wv = ((const float4*)w)[i];
    uint2 o;
    o.x = packh2(inv * xv.x * wv.x, inv * xv.y * wv.y);
    o.y = packh2(inv * xv.z * wv.z, inv * xv.w * wv.w);
    ((uint2*)(out + (size_t)row * D_))[i] = o;
}

// ---------------------------------------------------------------------------
// Single-fp16 HMMA causal flash attention, 2-stage KV cp.async pipeline.
// ---------------------------------------------------------------------------
#define AP     144
#define ATQ    0
#define ATKV   9216
#define AT_SMEM (9216 + 2 * 18432)

__global__ __launch_bounds__(128, 3) void attn_mma_kernel(
    const hf* __restrict__ qg, const hf* __restrict__ kg,
    const hf* __restrict__ vg, hf* __restrict__ oh) {
    extern __shared__ char smx[];
    uint32_t sb = smem_u32(smx);
    int tid = threadIdx.x, w = tid >> 5, lane = tid & 31;
    int qt = gridDim.x - 1 - blockIdx.x;
    int h = blockIdx.y, b = blockIdx.z;
    size_t base = (size_t)(b * H_ + h) * S_;
    int s0 = qt * 64;

#pragma unroll
    for (int i = 0; i < 4; i++) {
        int idx = i * 128 + tid;
        int row = idx >> 3, c = idx & 7;
        cp16(sb + ATQ + row * AP + c * 16, qg + (base + s0 + row) * DK_ + c * 8);
    }
    asm volatile("cp.async.commit_group;");

#define LOADKV(t, s)                                                           \
    {                                                                          \
        uint32_t kvb = sb + ATKV + (s) * 18432;                                \
        _Pragma("unroll")                                                      \
        for (int i = 0; i < 4; i++) {                                          \
            int idx = i * 128 + tid;                                           \
            int row = idx >> 3, c = idx & 7;                                   \
            size_t go = (base + (t) * 64 + row) * DK_ + c * 8;                 \
            cp16(kvb + row * AP + c * 16, kg + go);                            \
            cp16(kvb + 9216 + row * AP + c * 16, vg + go);                     \
        }                                                                      \
        asm volatile("cp.async.commit_group;");                                \
    }

    LOADKV(0, 0)
    asm volatile("cp.async.wait_group 1;");
    __syncthreads();

    uint32_t qf[4][4];
#pragma unroll
    for (int ks = 0; ks < 4; ks++) {
        uint32_t ar = sb + ATQ + (16 * w + (lane & 15)) * AP
                    + (ks * 16 + (lane >> 4) * 8) * 2;
        ldm4(qf[ks], ar);
    }

    float oacc[8][4];
#pragma unroll
    for (int j = 0; j < 8; j++)
#pragma unroll
        for (int t = 0; t < 4; t++) oacc[j][t] = 0.f;
    float m0 = -INFINITY, m1 = -INFINITY, l0 = 0.f, l1 = 0.f;
    int q0 = s0 + 16 * w + (lane >> 2);

    for (int kvt = 0; kvt <= qt; kvt++) {
        int s = kvt & 1;
        if (kvt < qt) {
            LOADKV(kvt + 1, s ^ 1)
            asm volatile("cp.async.wait_group 1;");
        } else {
            asm volatile("cp.async.wait_group 0;");
        }
        __syncthreads();

        uint32_t kvb = sb + ATKV + s * 18432;
        float sacc[8][4];
#pragma unroll
        for (int j = 0; j < 8; j++)
#pragma unroll
            for (int t = 0; t < 4; t++) sacc[j][t] = 0.f;
#pragma unroll
        for (int ks = 0; ks < 4; ks++) {
            uint32_t br = kvb + ((lane & 7) + ((lane >> 4) & 1) * 8) * AP
                        + (ks * 16 + ((lane >> 3) & 1) * 8) * 2;
#pragma unroll
            for (int g = 0; g < 4; g++) {
                uint32_t b4[4];
                ldm4(b4, br + g * 16 * AP);
                mmah(sacc[2 * g],     qf[ks], b4[0], b4[1]);
                mmah(sacc[2 * g + 1], qf[ks], b4[2], b4[3]);
            }
        }
#pragma unroll
        for (int j = 0; j < 8; j++)
#pragma unroll
            for (int t = 0; t < 4; t++) sacc[j][t] *= 0.125f;
        if (kvt == qt) {
            int cb = kvt * 64 + 2 * (lane & 3);
#pragma unroll
            for (int j = 0; j < 8; j++) {
                int kc = cb + 8 * j;
                if (kc     > q0)     sacc[j][0] = -INFINITY;
                if (kc + 1 > q0)     sacc[j][1] = -INFINITY;
                if (kc     > q0 + 8) sacc[j][2] = -INFINITY;
                if (kc + 1 > q0 + 8) sacc[j][3] = -INFINITY;
            }
        }
        float mx0 = -INFINITY, mx1 = -INFINITY;
#pragma unroll
        for (int j = 0; j < 8; j++) {
            mx0 = fmaxf(mx0, fmaxf(sacc[j][0], sacc[j][1]));
            mx1 = fmaxf(mx1, fmaxf(sacc[j][2], sacc[j][3]));
        }
        mx0 = fmaxf(mx0, __shfl_xor_sync(0xffffffffu, mx0, 1));
        mx0 = fmaxf(mx0, __shfl_xor_sync(0xffffffffu, mx0, 2));
        mx1 = fmaxf(mx1, __shfl_xor_sync(0xffffffffu, mx1, 1));
        mx1 = fmaxf(mx1, __shfl_xor_sync(0xffffffffu, mx1, 2));
        float mn0 = fmaxf(m0, mx0), mn1 = fmaxf(m1, mx1);
        float cr0 = __expf(m0 - mn0), cr1 = __expf(m1 - mn1);
        l0 *= cr0; l1 *= cr1;
#pragma unroll
        for (int j = 0; j < 8; j++) {
            oacc[j][0] *= cr0; oacc[j][1] *= cr0;
            oacc[j][2] *= cr1; oacc[j][3] *= cr1;
        }
        uint32_t pf[4][4];
#pragma unroll
        for (int j = 0; j < 8; j++) {
            float p0 = __expf(sacc[j][0] - mn0);
            float p1 = __expf(sacc[j][1] - mn0);
            float p2 = __expf(sacc[j][2] - mn1);
            float p3 = __expf(sacc[j][3] - mn1);
            l0 += p0 + p1; l1 += p2 + p3;
            pf[j >> 1][(j & 1) * 2]     = packh2(p0, p1);
            pf[j >> 1][(j & 1) * 2 + 1] = packh2(p2, p3);
        }
        m0 = mn0; m1 = mn1;
#pragma unroll
        for (int kt = 0; kt < 4; kt++) {
            uint32_t va = kvb + 9216 + (kt * 16 + (lane & 15)) * AP
                        + ((lane >> 4) * 8) * 2;
#pragma unroll
            for (int gn = 0; gn < 4; gn++) {
                uint32_t vb[4];
                ldm4t(vb, va + gn * 32);
                mmah(oacc[2 * gn],     pf[kt], vb[0], vb[1]);
                mmah(oacc[2 * gn + 1], pf[kt], vb[2], vb[3]);
            }
        }
        __syncthreads();
    }

    l0 += __shfl_xor_sync(0xffffffffu, l0, 1);
    l0 += __shfl_xor_sync(0xffffffffu, l0, 2);
    l1 += __shfl_xor_sync(0xffffffffu, l1, 1);
    l1 += __shfl_xor_sync(0xffffffffu, l1, 2);
    float i0 = 1.f / l0, i1 = 1.f / l1;

    size_t r0 = (size_t)(b * S_ + q0) * D_ + h * DK_;
    size_t r1 = (size_t)(b * S_ + q0 + 8) * D_ + h * DK_;
#pragma unroll
    for (int j = 0; j < 8; j++) {
        int dk0 = 8 * j + 2 * (lane & 3);
        *(uint32_t*)(oh + r0 + dk0) = packh2(oacc[j][0] * i0, oacc[j][1] * i0);
        *(uint32_t*)(oh + r1 + dk0) = packh2(oacc[j][2] * i1, oacc[j][3] * i1);
    }
}

// ---------------------------------------------------------------------------
// Launch (launch index 3 == qkv GEMM, targeted by ncu -s 5 -c 1)
// ---------------------------------------------------------------------------
extern "C" void kernel_launch(void* const* d_in, const int* in_sizes, int n_in,
                              void* d_out, int out_size) {
    const float* x   = (const float*)d_in[0];
    const float* w_q = (const float*)d_in[1];
    const float* w_k = (const float*)d_in[2];
    const float* w_v = (const float*)d_in[3];
    const float* w_o = (const float*)d_in[4];
    const float* ln1 = (const float*)d_in[5];
    const float* ln2 = (const float*)d_in[6];
    const float* w1  = (const float*)d_in[7];
    const float* w2  = (const float*)d_in[8];
    const float* w3  = (const float*)d_in[9];
    float* out = (float*)d_out;

    float *ffn, *x2;
    float2* rope;
    __nv_bfloat16 *sh;
    hf* wp;
    cudaGetSymbolAddress((void**)&ffn,  g_ffn);
    cudaGetSymbolAddress((void**)&x2,   g_x2);
    cudaGetSymbolAddress((void**)&rope, g_rope);
    cudaGetSymbolAddress((void**)&sh,   g_sh);
    cudaGetSymbolAddress((void**)&wp,   g_w);
    hf* qA    = (hf*)sh + OQ_;
    hf* kA    = (hf*)sh + OK_;
    hf* vA    = (hf*)sh + OV_;
    hf* hA    = (hf*)sh + OA_;
    hf* h2A   = (hf*)sh;
    hf* siluA = (hf*)ffn;

    cudaFuncSetAttribute(mma_gemm_kernel,
                         cudaFuncAttributeMaxDynamicSharedMemorySize, MG_SMEM);
    cudaFuncSetAttribute(mma_gemm_qkv_kernel,
                         cudaFuncAttributeMaxDynamicSharedMemorySize, MG_SMEM);
    cudaFuncSetAttribute(mma_gemm_swiglu_kernel,
                         cudaFuncAttributeMaxDynamicSharedMemorySize, MG_SMEM);
    cudaFuncSetAttribute(attn_mma_kernel,
                         cudaFuncAttributeMaxDynamicSharedMemorySize, AT_SMEM);

    // 0..2
    rope_table_kernel<<<(S_ * 32 + 255) / 256, 256>>>(rope);
    rmsnorm_h_kernel<<<M_, 256>>>(x, ln1, hA);
    wconv3_kernel<<<1024, 256>>>(w_q, w_k, w_v, wp + OW_Q);

    // 3 (ncu target): qkv GEMM -> roped fp16 q,k,v in [b,h,s,dk]
    mma_gemm_qkv_kernel<<<dim3(3072 / 128, M_ / 128), 256, MG_SMEM>>>(
        hA, wp + OW_Q, rope, (hf*)sh);

    // remaining weight converts
    wconv_kernel<<<256, 256>>>(w_o, wp + OW_O, 262144);
    wconv13_kernel<<<4096, 256>>>(w1, w3, wp + OW_1);
    wconv_kernel<<<1024, 256>>>(w2, wp + OW_2, 1048576);

    // attention -> fp16 at OA_
    attn_mma_kernel<<<dim3(S_ / 64, H_, B_), 128, AT_SMEM>>>(qA, kA, vA, hA);

    // x2 = x + attn @ w_o^T
    mma_gemm_kernel<<<dim3(D_ / 128, M_ / 128), 256, MG_SMEM>>>(
        hA, wp + OW_O, x, x2, M_, D_, D_);

    // h2 = rmsnorm(x2)
    rmsnorm_h_kernel<<<M_, 256>>>(x2, ln2, h2A);

    // [u|g] GEMM + SwiGLU
    mma_gemm_swiglu_kernel<<<dim3(8192 / 128, M_ / 128), 256, MG_SMEM>>>(
        h2A, wp + OW_1, siluA);

    // out = x2 + silu @ w2^T
    mma_gemm_kernel<<<dim3(D_ / 128, M_ / 128), 256, MG_SMEM>>>(
        siluA, wp + OW_2, x2, out, M_, D_, DFF_);
}